// round 7
// baseline (speedup 1.0000x reference)
#include <cuda_runtime.h>
#include <math.h>
#include <stdint.h>

// MADE/IAF layer via per-warp tf32 mma.sync (compute_103-safe).
//   zp = z[:, perm]
//   h  = relu(zp @ (W1*M1) + b1)          M=4096 K=1024 N=4096
//   r  = h @ (W2*M2) + b2                 M=4096 K=4096 N=2048
//   x  = zp*exp(log_s)+mu ; scatter by perm ; log_det = sum(log_s)
// Masks (index functions, fused into B staging):
//   M1[d,h] = (h % (D-1)) >= d
//   M2[h,o] = (o % D)     >  (h % (D-1))
// Block-sparsity: all-zero masked B k-tiles are skipped.
// Grid: N-blocks fast (A row-block reuse in L2), heavy N-blocks first.

#define BM 128
#define BN 128
#define BK 32
#define NTH 256
#define SMEM_BYTES (4 * 16384)   // As0,Bs0,As1,Bs1 (16KB each)

__device__ float g_zp[4096L * 1024];   // 16.8 MB
__device__ float g_h [4096L * 4096];   // 67.1 MB
__device__ float g_res[4096L * 2048];  // 33.6 MB

__device__ __forceinline__ uint32_t tf32u(float x) {
    uint32_t y; asm("cvt.rna.tf32.f32 %0, %1;" : "=r"(y) : "f"(x)); return y;
}
__device__ __forceinline__ void mma8(float* d,
                                     uint32_t a0, uint32_t a1, uint32_t a2, uint32_t a3,
                                     uint32_t b0, uint32_t b1) {
    asm volatile(
        "mma.sync.aligned.m16n8k8.row.col.f32.tf32.tf32.f32 "
        "{%0,%1,%2,%3}, {%4,%5,%6,%7}, {%8,%9}, {%0,%1,%2,%3};"
        : "+f"(d[0]), "+f"(d[1]), "+f"(d[2]), "+f"(d[3])
        : "r"(a0), "r"(a1), "r"(a2), "r"(a3), "r"(b0), "r"(b1));
}
// swizzled smem byte offset for element (k, x) of a [BK][128] fp32 tile
__device__ __forceinline__ uint32_t swz(int k, int x) {
    return (uint32_t)(((k << 7) + (x ^ ((((k & 3) ^ ((k >> 2) & 3))) << 3))) << 2);
}
__device__ __forceinline__ uint32_t lds32(const char* p) {
    return *(const uint32_t*)p;
}

__global__ void gather_zp_kernel(const float* __restrict__ z,
                                 const int* __restrict__ perm,
                                 int Brows, int D) {
    int idx = blockIdx.x * blockDim.x + threadIdx.x;
    if (idx < Brows * D) {
        int b = idx / D;
        int d = idx - b * D;
        g_zp[idx] = z[(size_t)b * D + perm[d]];
    }
}

// MODE 1: A=g_zp, Bw=W1, mask1, bias+relu, C=g_h
// MODE 2: A=g_h,  Bw=W2, mask2, bias,      C=g_res
template <int MODE>
__global__ void __launch_bounds__(NTH, 1)
gemm_mma(const float* __restrict__ Bw, const float* __restrict__ bias,
         int N, int K, int D)
{
    const float* __restrict__ A = (MODE == 1) ? g_zp : g_h;
    float* __restrict__ C       = (MODE == 1) ? g_h  : g_res;

    extern __shared__ char sm[];

    const int tid  = threadIdx.x;
    const int wid  = tid >> 5;
    const int lane = tid & 31;
    const int gq   = lane >> 2;
    const int tq   = lane & 3;
    const int Dm1  = D - 1;

    // N-blocks on blockIdx.x (fast dim), remapped so heavy blocks (high
    // j mod (D/BN), i.e. high maxkey -> more active k-tiles) launch first.
    const int NBLK = N / BN;            // 32 (g1) / 16 (g2)
    const int P    = D / BN;            // 8
    const int G    = NBLK / P;          // 4 / 2
    const int jc   = blockIdx.x;
    const int jreal = (jc % G) * P + (P - 1 - jc / G);
    const int col0 = jreal * BN;
    const int row0 = blockIdx.y * BM;

    const int mwarp = (wid & 1) * 64;
    const int nwarp = (wid >> 1) * 32;

    // ---- tile-skip bounds from mask structure ----
    int maxkey;
    if (MODE == 1) {
        int m0 = col0 % Dm1;
        maxkey = (m0 + BN - 1 >= Dm1) ? (Dm1 - 1) : (m0 + BN - 1);
    } else {
        maxkey = (col0 % D) + BN - 1;   // BN | D alignment: no wrap
    }
    const int nT = K / BK;
    const int nT1 = (MODE == 1) ? min(nT, maxkey / BK + 1) : nT;

    // ---- staging maps ----
    int aq[4], am[4]; const float* aglob[4]; uint32_t aoff[4][4];
    int bk[4], bn0[4]; const float* bglob[4]; uint32_t boff[4]; int key0[4];
#pragma unroll
    for (int i = 0; i < 4; i++) {
        int fa = tid + i * NTH;
        aq[i] = fa & 7;  am[i] = fa >> 3;
        aglob[i] = A + (size_t)(row0 + am[i]) * K + aq[i] * 4;
#pragma unroll
        for (int j = 0; j < 4; j++)
            aoff[i][j] = swz(4 * aq[i] + j, am[i]);

        int fb = tid + i * NTH;
        bk[i] = fb >> 5;  bn0[i] = (fb & 31) * 4;
        bglob[i] = Bw + (size_t)bk[i] * N + col0 + bn0[i];
        boff[i] = swz(bk[i], bn0[i]);
        int c = col0 + bn0[i];
        key0[i] = (MODE == 1) ? (c % Dm1) : (c % D);
    }

    float acc[4][4][4];
#pragma unroll
    for (int mt = 0; mt < 4; mt++)
#pragma unroll
        for (int nt = 0; nt < 4; nt++)
#pragma unroll
            for (int e = 0; e < 4; e++) acc[mt][nt][e] = 0.f;

#define STAGE_TILE(TT, AS, BS)                                             \
    {                                                                       \
        char* as_ = (AS); char* bs_ = (BS);                                 \
        _Pragma("unroll")                                                   \
        for (int i = 0; i < 4; i++) {                                       \
            float4 v = *(const float4*)(aglob[i] + (TT) * BK);              \
            *(uint32_t*)(as_ + aoff[i][0]) = tf32u(v.x);                    \
            *(uint32_t*)(as_ + aoff[i][1]) = tf32u(v.y);                    \
            *(uint32_t*)(as_ + aoff[i][2]) = tf32u(v.z);                    \
            *(uint32_t*)(as_ + aoff[i][3]) = tf32u(v.w);                    \
        }                                                                   \
        _Pragma("unroll")                                                   \
        for (int i = 0; i < 4; i++) {                                       \
            float4 v = *(const float4*)(bglob[i] + (size_t)(TT) * BK * N);  \
            int kg = (TT) * BK + bk[i];                                     \
            int km = (MODE == 1) ? kg : (kg % Dm1);                         \
            uint4 u; int ky;                                                \
            ky = key0[i] + 0; if (MODE == 1 && ky >= Dm1) ky -= Dm1;        \
            u.x = ((MODE == 1) ? (ky >= km) : (ky > km)) ? tf32u(v.x) : 0u; \
            ky = key0[i] + 1; if (MODE == 1 && ky >= Dm1) ky -= Dm1;        \
            u.y = ((MODE == 1) ? (ky >= km) : (ky > km)) ? tf32u(v.y) : 0u; \
            ky = key0[i] + 2; if (MODE == 1 && ky >= Dm1) ky -= Dm1;        \
            u.z = ((MODE == 1) ? (ky >= km) : (ky > km)) ? tf32u(v.z) : 0u; \
            ky = key0[i] + 3; if (MODE == 1 && ky >= Dm1) ky -= Dm1;        \
            u.w = ((MODE == 1) ? (ky >= km) : (ky > km)) ? tf32u(v.w) : 0u; \
            *(uint4*)(bs_ + boff[i]) = u;                                   \
        }                                                                   \
    }

#define LOAD_FRAG(KS, AF, BF, AS, BS)                                      \
    {                                                                       \
        const int k0_ = (KS) * 8 + tq;                                      \
        _Pragma("unroll")                                                   \
        for (int mt = 0; mt < 4; mt++) {                                    \
            int m_ = mwarp + mt * 16 + gq;                                  \
            (AF)[mt][0] = lds32((AS) + swz(k0_,     m_));                   \
            (AF)[mt][1] = lds32((AS) + swz(k0_,     m_ + 8));               \
            (AF)[mt][2] = lds32((AS) + swz(k0_ + 4, m_));                   \
            (AF)[mt][3] = lds32((AS) + swz(k0_ + 4, m_ + 8));               \
        }                                                                   \
        _Pragma("unroll")                                                   \
        for (int nt = 0; nt < 4; nt++) {                                    \
            int n_ = nwarp + nt * 8 + gq;                                   \
            (BF)[nt][0] = lds32((BS) + swz(k0_,     n_));                   \
            (BF)[nt][1] = lds32((BS) + swz(k0_ + 4, n_));                   \
        }                                                                   \
    }

    int tcur = 0;
    STAGE_TILE(0, sm, sm + 16384);
    __syncthreads();

    int buf = 0;
    for (;;) {
        int tn = tcur + 1;
        if (MODE == 1) {
            if (tn >= nT1) tn = nT;
        } else {
            while (tn < nT) {
                int r = (tn * BK) % Dm1;
                int minh = (r + BK - 1 > Dm1 - 1) ? 0 : r;   // wrap hits 0
                if (minh < maxkey) break;
                tn++;
            }
        }
        const bool more = (tn < nT);

        float4 apre[4], bpre[4];
        if (more) {
#pragma unroll
            for (int i = 0; i < 4; i++)
                apre[i] = *(const float4*)(aglob[i] + tn * BK);
#pragma unroll
            for (int i = 0; i < 4; i++)
                bpre[i] = *(const float4*)(bglob[i] + (size_t)tn * BK * N);
        }

        const char* as = sm + buf * 32768;
        const char* bs = as + 16384;
        uint32_t af[2][4][4], bf[2][4][2];
        LOAD_FRAG(0, af[0], bf[0], as, bs);
#pragma unroll
        for (int ks = 0; ks < 4; ks++) {
            const int cur = ks & 1;
            if (ks < 3) LOAD_FRAG(ks + 1, af[cur ^ 1], bf[cur ^ 1], as, bs);
#pragma unroll
            for (int mt = 0; mt < 4; mt++)
#pragma unroll
                for (int nt = 0; nt < 4; nt++)
                    mma8(acc[mt][nt],
                         af[cur][mt][0], af[cur][mt][1], af[cur][mt][2], af[cur][mt][3],
                         bf[cur][nt][0], bf[cur][nt][1]);
        }

        if (!more) break;

        {
            char* asw = sm + (buf ^ 1) * 32768;
            char* bsw = asw + 16384;
#pragma unroll
            for (int i = 0; i < 4; i++) {
                *(uint32_t*)(asw + aoff[i][0]) = tf32u(apre[i].x);
                *(uint32_t*)(asw + aoff[i][1]) = tf32u(apre[i].y);
                *(uint32_t*)(asw + aoff[i][2]) = tf32u(apre[i].z);
                *(uint32_t*)(asw + aoff[i][3]) = tf32u(apre[i].w);
            }
#pragma unroll
            for (int i = 0; i < 4; i++) {
                int kg = tn * BK + bk[i];
                int km = (MODE == 1) ? kg : (kg % Dm1);
                uint4 u; int ky;
                ky = key0[i] + 0; if (MODE == 1 && ky >= Dm1) ky -= Dm1;
                u.x = ((MODE == 1) ? (ky >= km) : (ky > km)) ? tf32u(bpre[i].x) : 0u;
                ky = key0[i] + 1; if (MODE == 1 && ky >= Dm1) ky -= Dm1;
                u.y = ((MODE == 1) ? (ky >= km) : (ky > km)) ? tf32u(bpre[i].y) : 0u;
                ky = key0[i] + 2; if (MODE == 1 && ky >= Dm1) ky -= Dm1;
                u.z = ((MODE == 1) ? (ky >= km) : (ky > km)) ? tf32u(bpre[i].z) : 0u;
                ky = key0[i] + 3; if (MODE == 1 && ky >= Dm1) ky -= Dm1;
                u.w = ((MODE == 1) ? (ky >= km) : (ky > km)) ? tf32u(bpre[i].w) : 0u;
                *(uint4*)(bsw + boff[i]) = u;
            }
        }
        __syncthreads();
        buf ^= 1;
        tcur = tn;
    }

    // ---- epilogue: acc -> bias(+relu) -> C ----
#pragma unroll
    for (int mt = 0; mt < 4; mt++) {
        int r0 = row0 + mwarp + mt * 16 + gq;
#pragma unroll
        for (int nt = 0; nt < 4; nt++) {
            int c = col0 + nwarp + nt * 8 + 2 * tq;
            float bx = bias[c], by = bias[c + 1];
            float2 v0, v1;
            v0.x = acc[mt][nt][0] + bx;  v0.y = acc[mt][nt][1] + by;
            v1.x = acc[mt][nt][2] + bx;  v1.y = acc[mt][nt][3] + by;
            if (MODE == 1) {
                v0.x = fmaxf(v0.x, 0.f); v0.y = fmaxf(v0.y, 0.f);
                v1.x = fmaxf(v1.x, 0.f); v1.y = fmaxf(v1.y, 0.f);
            }
            *(float2*)(C + (size_t)r0 * N + c)       = v0;
            *(float2*)(C + (size_t)(r0 + 8) * N + c) = v1;
        }
    }
#undef STAGE_TILE
#undef LOAD_FRAG
}

__global__ void finish_kernel(const int* __restrict__ perm,
                              float* __restrict__ out,
                              int Brows, int D, int out_size)
{
    int b = blockIdx.x;
    int tid = threadIdx.x;
    const float* mu = g_res + (size_t)b * 2 * D;
    const float* ls = mu + D;
    const float* zp = g_zp + (size_t)b * D;

    float partial = 0.f;
    for (int d = tid; d < D; d += blockDim.x) {
        float l = ls[d];
        float x = zp[d] * expf(l) + mu[d];
        out[(size_t)b * D + perm[d]] = x;
        partial += l;
    }

    __shared__ float red[256];
    red[tid] = partial;
    __syncthreads();
    for (int s = 128; s > 0; s >>= 1) {
        if (tid < s) red[tid] += red[tid + s];
        __syncthreads();
    }
    if (tid == 0 && out_size >= Brows * D + Brows)
        out[(size_t)Brows * D + b] = red[0];
}

extern "C" void kernel_launch(void* const* d_in, const int* in_sizes, int n_in,
                              void* d_out, int out_size)
{
    const float* z   = (const float*)d_in[0];
    const float* W1  = (const float*)d_in[1];
    const float* b1  = (const float*)d_in[2];
    const float* W2  = (const float*)d_in[3];
    const float* b2  = (const float*)d_in[4];
    const int*  perm = (const int*)d_in[5];

    const int D     = in_sizes[5];          // 1024
    const int H     = in_sizes[2];          // 4096
    const int Brows = in_sizes[0] / D;      // 4096
    const int N2    = in_sizes[4];          // 2048

    float* out = (float*)d_out;

    cudaFuncSetAttribute(gemm_mma<1>, cudaFuncAttributeMaxDynamicSharedMemorySize, SMEM_BYTES);
    cudaFuncSetAttribute(gemm_mma<2>, cudaFuncAttributeMaxDynamicSharedMemorySize, SMEM_BYTES);

    gather_zp_kernel<<<(Brows * D + 255) / 256, 256>>>(z, perm, Brows, D);

    // N-blocks fast: a wave spans few row-blocks x all col-blocks ->
    // A row-block read from DRAM once, L2-served to the rest; W resident.
    dim3 g1(H / BN, Brows / BM);
    gemm_mma<1><<<g1, NTH, SMEM_BYTES>>>(W1, b1, H, D, D);

    dim3 g2(N2 / BN, Brows / BM);
    gemm_mma<2><<<g2, NTH, SMEM_BYTES>>>(W2, b2, N2, H, D);

    finish_kernel<<<Brows, 256>>>(perm, out, Brows, D, out_size);
}

// round 8
// speedup vs baseline: 1.4080x; 1.4080x over previous
#include <cuda_runtime.h>
#include <math.h>
#include <stdint.h>

// MADE/IAF layer via per-warp fp16 mma.sync m16n8k16 (compute_103-safe).
//   zp = z[:, perm]
//   h  = relu(zp @ (W1*M1) + b1)          M=4096 K=1024 N=4096
//   r  = h @ (W2*M2) + b2                 M=4096 K=4096 N=2048
//   x  = zp*exp(log_s)+mu ; scatter by perm ; log_det = sum(log_s)
// Masks (index functions, fused into B staging):
//   M1[d,h] = (h % (D-1)) >= d
//   M2[h,o] = (o % D)     >  (h % (D-1))
// All-zero masked B k-tiles are skipped (exact-zero contributions).
// fp16 inputs (11-bit significand == tf32), fp32 accumulate.

#define BM 128
#define BN 128
#define BK 32
#define NTH 256

__device__ float g_zp[4096L * 1024];   // 16.8 MB
__device__ float g_h [4096L * 4096];   // 67.1 MB
__device__ float g_res[4096L * 2048];  // 33.6 MB

// pack two floats into f16x2: lo -> low half, hi -> high half
__device__ __forceinline__ uint32_t h2pack(float lo, float hi) {
    uint32_t w;
    asm("cvt.rn.f16x2.f32 %0, %1, %2;" : "=r"(w) : "f"(hi), "f"(lo));
    return w;
}
__device__ __forceinline__ void mma16(float* d,
                                      uint32_t a0, uint32_t a1, uint32_t a2, uint32_t a3,
                                      uint32_t b0, uint32_t b1) {
    asm volatile(
        "mma.sync.aligned.m16n8k16.row.col.f32.f16.f16.f32 "
        "{%0,%1,%2,%3}, {%4,%5,%6,%7}, {%8,%9}, {%0,%1,%2,%3};"
        : "+f"(d[0]), "+f"(d[1]), "+f"(d[2]), "+f"(d[3])
        : "r"(a0), "r"(a1), "r"(a2), "r"(a3), "r"(b0), "r"(b1));
}
// swizzled byte offset of 32-bit word (kp, w) in a [16][128]-word tile
__device__ __forceinline__ uint32_t swz16(int kp, int w) {
    return (uint32_t)(((kp << 7) + (w ^ ((((kp & 3) ^ ((kp >> 2) & 3))) << 3))) << 2);
}
__device__ __forceinline__ uint32_t lds32(const char* p) {
    return *(const uint32_t*)p;
}

__global__ void gather_zp_kernel(const float* __restrict__ z,
                                 const int* __restrict__ perm,
                                 int Brows, int D) {
    int idx = blockIdx.x * blockDim.x + threadIdx.x;
    if (idx < Brows * D) {
        int b = idx / D;
        int d = idx - b * D;
        g_zp[idx] = z[(size_t)b * D + perm[d]];
    }
}

// MODE 1: A=g_zp, Bw=W1, mask1, bias+relu, C=g_h
// MODE 2: A=g_h,  Bw=W2, mask2, bias,      C=g_res
template <int MODE>
__global__ void __launch_bounds__(NTH, 1)
gemm_mma(const float* __restrict__ Bw, const float* __restrict__ bias,
         int N, int K, int D)
{
    const float* __restrict__ A = (MODE == 1) ? g_zp : g_h;
    float* __restrict__ C       = (MODE == 1) ? g_h  : g_res;

    // 2 stages x (A 8KB + B 8KB) = 32KB
    __shared__ char sm[32768];

    const int tid  = threadIdx.x;
    const int wid  = tid >> 5;
    const int lane = tid & 31;
    const int gq   = lane >> 2;
    const int tq   = lane & 3;
    const int row0 = blockIdx.x * BM;   // M fast (round-6 winner)
    const int col0 = blockIdx.y * BN;
    const int Dm1  = D - 1;

    const int mwarp = (wid & 1) * 64;
    const int nwarp = (wid >> 1) * 32;

    // ---- tile-skip bounds from mask structure ----
    int maxkey;
    if (MODE == 1) {
        int m0 = col0 % Dm1;
        maxkey = (m0 + BN - 1 >= Dm1) ? (Dm1 - 1) : (m0 + BN - 1);
    } else {
        maxkey = (col0 % D) + BN - 1;   // BN | D: no wrap
    }
    const int nT = K / BK;
    const int nT1 = (MODE == 1) ? min(nT, maxkey / BK + 1) : nT;

    // ---- staging maps ----
    // A: fa = tid + i*256 (i<4): m = fa>>3, q = fa&7 -> k0 = 4q. LDG.128
    //    coalesced (8 lanes span one row's 32 floats). 2 STS.32 per float4.
    int am[4], aq[4]; const float* aglob[4]; uint32_t aoff[4][2];
#pragma unroll
    for (int i = 0; i < 4; i++) {
        int fa = tid + i * NTH;
        am[i] = fa >> 3;  aq[i] = fa & 7;
        aglob[i] = A + (size_t)(row0 + am[i]) * K + aq[i] * 4;
        aoff[i][0] = swz16(2 * aq[i],     am[i]);
        aoff[i][1] = swz16(2 * aq[i] + 1, am[i]);
    }
    // B: slot = tid + i*256 (i<2): kp = slot>>5, n0 = (slot&31)*4.
    //    Two LDG.128 from adjacent k-rows -> pairs pack into one STS.128.
    int bkp[2]; const float* bglob[2]; uint32_t boff[2]; int bkey[2][4];
#pragma unroll
    for (int i = 0; i < 2; i++) {
        int s = tid + i * NTH;
        bkp[i] = s >> 5;
        int n0 = (s & 31) * 4;
        bglob[i] = Bw + (size_t)(2 * bkp[i]) * N + col0 + n0;
        boff[i] = swz16(bkp[i], n0);
#pragma unroll
        for (int j = 0; j < 4; j++) {
            int c = col0 + n0 + j;
            bkey[i][j] = (MODE == 1) ? (c % Dm1) : (c % D);
        }
    }

    float acc[4][4][4];
#pragma unroll
    for (int mt = 0; mt < 4; mt++)
#pragma unroll
        for (int nt = 0; nt < 4; nt++)
#pragma unroll
            for (int e = 0; e < 4; e++) acc[mt][nt][e] = 0.f;

#define BPASS(KY, KM) ((MODE == 1) ? ((KY) >= (KM)) : ((KY) > (KM)))

#define STAGE_A(VA, AS)                                                    \
    _Pragma("unroll")                                                      \
    for (int i = 0; i < 4; i++) {                                          \
        *(uint32_t*)((AS) + aoff[i][0]) = h2pack((VA)[i].x, (VA)[i].y);    \
        *(uint32_t*)((AS) + aoff[i][1]) = h2pack((VA)[i].z, (VA)[i].w);    \
    }

#define STAGE_B(TT, V0, V1, BS)                                            \
    _Pragma("unroll")                                                      \
    for (int i = 0; i < 2; i++) {                                          \
        int kg  = (TT) * BK + 2 * bkp[i];                                  \
        int km0 = (MODE == 1) ? kg       : (kg % Dm1);                     \
        int km1 = (MODE == 1) ? (kg + 1) : ((kg + 1) % Dm1);               \
        uint4 u;                                                           \
        u.x = h2pack(BPASS(bkey[i][0], km0) ? (V0)[i].x : 0.f,             \
                     BPASS(bkey[i][0], km1) ? (V1)[i].x : 0.f);            \
        u.y = h2pack(BPASS(bkey[i][1], km0) ? (V0)[i].y : 0.f,             \
                     BPASS(bkey[i][1], km1) ? (V1)[i].y : 0.f);            \
        u.z = h2pack(BPASS(bkey[i][2], km0) ? (V0)[i].z : 0.f,             \
                     BPASS(bkey[i][2], km1) ? (V1)[i].z : 0.f);            \
        u.w = h2pack(BPASS(bkey[i][3], km0) ? (V0)[i].w : 0.f,             \
                     BPASS(bkey[i][3], km1) ? (V1)[i].w : 0.f);            \
        *(uint4*)((BS) + boff[i]) = u;                                     \
    }

#define LOAD_FRAG(KS, AF, BF, AS, BS)                                      \
    {                                                                       \
        const int kpl = (KS) * 8 + tq;                                     \
        const int kph = kpl + 4;                                           \
        _Pragma("unroll")                                                  \
        for (int mt = 0; mt < 4; mt++) {                                   \
            int m_ = mwarp + mt * 16 + gq;                                 \
            (AF)[mt][0] = lds32((AS) + swz16(kpl, m_));                    \
            (AF)[mt][1] = lds32((AS) + swz16(kpl, m_ + 8));                \
            (AF)[mt][2] = lds32((AS) + swz16(kph, m_));                    \
            (AF)[mt][3] = lds32((AS) + swz16(kph, m_ + 8));                \
        }                                                                  \
        _Pragma("unroll")                                                  \
        for (int nt = 0; nt < 4; nt++) {                                   \
            int n_ = nwarp + nt * 8 + gq;                                  \
            (BF)[nt][0] = lds32((BS) + swz16(kpl, n_));                    \
            (BF)[nt][1] = lds32((BS) + swz16(kph, n_));                    \
        }                                                                  \
    }

    // ---- stage tile 0 (always active) ----
    int tcur = 0;
    {
        float4 va[4], v0[2], v1[2];
#pragma unroll
        for (int i = 0; i < 4; i++) va[i] = *(const float4*)(aglob[i]);
#pragma unroll
        for (int i = 0; i < 2; i++) {
            v0[i] = *(const float4*)(bglob[i]);
            v1[i] = *(const float4*)(bglob[i] + N);
        }
        STAGE_A(va, sm);
        STAGE_B(0, v0, v1, sm + 8192);
    }
    __syncthreads();

    int buf = 0;
    for (;;) {
        // next active k-tile
        int tn = tcur + 1;
        if (MODE == 1) {
            if (tn >= nT1) tn = nT;
        } else {
            while (tn < nT) {
                int r = (tn * BK) % Dm1;
                int minh = (r + BK - 1 > Dm1 - 1) ? 0 : r;   // wrap hits 0
                if (minh < maxkey) break;
                tn++;
            }
        }
        const bool more = (tn < nT);

        float4 apre[4], bpre0[2], bpre1[2];
        if (more) {
#pragma unroll
            for (int i = 0; i < 4; i++)
                apre[i] = *(const float4*)(aglob[i] + tn * BK);
#pragma unroll
            for (int i = 0; i < 2; i++) {
                const float* p = bglob[i] + (size_t)tn * BK * N;
                bpre0[i] = *(const float4*)(p);
                bpre1[i] = *(const float4*)(p + N);
            }
        }

        // ---- compute on buffer buf; 2 k16 steps, fragment ping-pong ----
        const char* as = sm + buf * 16384;
        const char* bs = as + 8192;
        uint32_t af[2][4][4], bf[2][4][2];
        LOAD_FRAG(0, af[0], bf[0], as, bs);
        LOAD_FRAG(1, af[1], bf[1], as, bs);
#pragma unroll
        for (int ks = 0; ks < 2; ks++)
#pragma unroll
            for (int mt = 0; mt < 4; mt++)
#pragma unroll
                for (int nt = 0; nt < 4; nt++)
                    mma16(acc[mt][nt],
                          af[ks][mt][0], af[ks][mt][1], af[ks][mt][2], af[ks][mt][3],
                          bf[ks][nt][0], bf[ks][nt][1]);

        if (!more) break;

        {
            char* asw = sm + (buf ^ 1) * 16384;
            char* bsw = asw + 8192;
            STAGE_A(apre, asw);
            STAGE_B(tn, bpre0, bpre1, bsw);
        }
        __syncthreads();
        buf ^= 1;
        tcur = tn;
    }

    // ---- epilogue: acc -> bias(+relu) -> C ----
#pragma unroll
    for (int mt = 0; mt < 4; mt++) {
        int r0 = row0 + mwarp + mt * 16 + gq;
#pragma unroll
        for (int nt = 0; nt < 4; nt++) {
            int c = col0 + nwarp + nt * 8 + 2 * tq;
            float bx = bias[c], by = bias[c + 1];
            float2 v0, v1;
            v0.x = acc[mt][nt][0] + bx;  v0.y = acc[mt][nt][1] + by;
            v1.x = acc[mt][nt][2] + bx;  v1.y = acc[mt][nt][3] + by;
            if (MODE == 1) {
                v0.x = fmaxf(v0.x, 0.f); v0.y = fmaxf(v0.y, 0.f);
                v1.x = fmaxf(v1.x, 0.f); v1.y = fmaxf(v1.y, 0.f);
            }
            *(float2*)(C + (size_t)r0 * N + c)       = v0;
            *(float2*)(C + (size_t)(r0 + 8) * N + c) = v1;
        }
    }
#undef STAGE_A
#undef STAGE_B
#undef LOAD_FRAG
#undef BPASS
}

__global__ void finish_kernel(const int* __restrict__ perm,
                              float* __restrict__ out,
                              int Brows, int D, int out_size)
{
    int b = blockIdx.x;
    int tid = threadIdx.x;
    const float* mu = g_res + (size_t)b * 2 * D;
    const float* ls = mu + D;
    const float* zp = g_zp + (size_t)b * D;

    float partial = 0.f;
    for (int d = tid; d < D; d += blockDim.x) {
        float l = ls[d];
        float x = zp[d] * expf(l) + mu[d];
        out[(size_t)b * D + perm[d]] = x;
        partial += l;
    }

    __shared__ float red[256];
    red[tid] = partial;
    __syncthreads();
    for (int s = 128; s > 0; s >>= 1) {
        if (tid < s) red[tid] += red[tid + s];
        __syncthreads();
    }
    if (tid == 0 && out_size >= Brows * D + Brows)
        out[(size_t)Brows * D + b] = red[0];
}

extern "C" void kernel_launch(void* const* d_in, const int* in_sizes, int n_in,
                              void* d_out, int out_size)
{
    const float* z   = (const float*)d_in[0];
    const float* W1  = (const float*)d_in[1];
    const float* b1  = (const float*)d_in[2];
    const float* W2  = (const float*)d_in[3];
    const float* b2  = (const float*)d_in[4];
    const int*  perm = (const int*)d_in[5];

    const int D     = in_sizes[5];          // 1024
    const int H     = in_sizes[2];          // 4096
    const int Brows = in_sizes[0] / D;      // 4096
    const int N2    = in_sizes[4];          // 2048

    float* out = (float*)d_out;

    gather_zp_kernel<<<(Brows * D + 255) / 256, 256>>>(z, perm, Brows, D);

    dim3 g1(Brows / BM, H / BN);   // M fast (round-6 winner)
    gemm_mma<1><<<g1, NTH>>>(W1, b1, H, D, D);

    dim3 g2(Brows / BM, N2 / BN);
    gemm_mma<2><<<g2, NTH>>>(W2, b2, N2, H, D);

    finish_kernel<<<Brows, 256>>>(perm, out, Brows, D, out_size);
}

// round 10
// speedup vs baseline: 1.9970x; 1.4183x over previous
#include <cuda_runtime.h>
#include <cuda_fp16.h>
#include <math.h>
#include <stdint.h>

// MADE/IAF layer, fp16 mma.sync m16n8k16 + cp.async pipeline (compute_103-safe).
//   zp = z[:, perm]
//   h  = relu(zp @ (W1*M1) + b1)          M=4096 K=1024 N=4096
//   r  = h @ (W2*M2) + b2                 M=4096 K=4096 N=2048
//   x  = zp*exp(log_s)+mu ; scatter by perm ; log_det = sum(log_s)
// Masks baked into transposed fp16 weights at prep time:
//   M1[d,h] = (h % (D-1)) >= d ;  M2[h,o] = (o % D) > (h % (D-1))
// All-zero masked B k-tiles skipped (exact-zero contributions).

#define BM 128
#define BN 128
#define BK 32
#define NTH 256
#define NSTG 4
#define STG_BYTES 16384           // A 8KB + B 8KB per stage
#define SMEM_TOTAL (NSTG * STG_BYTES)

__device__ __half g_zph[4096L * 1024];   //  8.4 MB  zp fp16 [m][D]
__device__ __half g_ht [4096L * 4096];   // 33.6 MB  h  fp16 [m][H]
__device__ __half g_w1t[4096L * 1024];   //  8.4 MB  (W1*M1)^T fp16 [H][D]
__device__ __half g_w2t[2048L * 4096];   // 16.8 MB  (W2*M2)^T fp16 [2D][H]
__device__ float  g_res[4096L * 2048];   // 33.6 MB

__device__ __forceinline__ uint32_t smem_u32(const void* p) {
    uint32_t a;
    asm("{ .reg .u64 t; cvta.to.shared.u64 t, %1; cvt.u32.u64 %0, t; }" : "=r"(a) : "l"(p));
    return a;
}
__device__ __forceinline__ uint32_t h2pack(float lo, float hi) {
    uint32_t w;
    asm("cvt.rn.f16x2.f32 %0, %1, %2;" : "=r"(w) : "f"(hi), "f"(lo));
    return w;
}
__device__ __forceinline__ void mma16(float* d,
                                      uint32_t a0, uint32_t a1, uint32_t a2, uint32_t a3,
                                      uint32_t b0, uint32_t b1) {
    asm volatile(
        "mma.sync.aligned.m16n8k16.row.col.f32.f16.f16.f32 "
        "{%0,%1,%2,%3}, {%4,%5,%6,%7}, {%8,%9}, {%0,%1,%2,%3};"
        : "+f"(d[0]), "+f"(d[1]), "+f"(d[2]), "+f"(d[3])
        : "r"(a0), "r"(a1), "r"(a2), "r"(a3), "r"(b0), "r"(b1));
}
// byte offset of 32-bit word (row r, k-pair kp) in a [128 rows][16 words] tile
// swizzle: kp ^= ((r>>1)&3)<<2  -> all fragment LDS conflict-free, 16B-aligned chunks
__device__ __forceinline__ uint32_t woff(int r, int kp) {
    return (uint32_t)((r << 6) + ((kp ^ (((r >> 1) & 3) << 2)) << 2));
}
__device__ __forceinline__ uint32_t ldsw(uint32_t addr) {
    uint32_t v;
    asm volatile("ld.shared.b32 %0, [%1];" : "=r"(v) : "r"(addr));
    return v;
}
#define CPA16(dst, src) \
    asm volatile("cp.async.cg.shared.global [%0], [%1], 16;" :: "r"(dst), "l"(src))
#define CPA_COMMIT() asm volatile("cp.async.commit_group;" ::: "memory")
#define CPA_WAIT2()  asm volatile("cp.async.wait_group 2;" ::: "memory")

// ---- prep: masked transpose W[K][N] -> Wt[N][K] fp16 ----
// MODE 1: keep if (n % (D-1)) >= k        (W1)
// MODE 2: keep if (n % D)     >  (k % (D-1))   (W2)
template <int MODE>
__global__ void wt_kernel(const float* __restrict__ W, __half* __restrict__ Wt,
                          int K, int N, int D)
{
    __shared__ float tile[32][33];
    int k0 = blockIdx.x * 32, n0 = blockIdx.y * 32;
    int x = threadIdx.x, y = threadIdx.y;    // 32 x 8
#pragma unroll
    for (int r = 0; r < 32; r += 8)
        tile[y + r][x] = W[(size_t)(k0 + y + r) * N + n0 + x];
    __syncthreads();
    int Dm1 = D - 1;
#pragma unroll
    for (int r = 0; r < 32; r += 8) {
        int n = n0 + y + r, k = k0 + x;
        float v = tile[x][y + r];
        bool keep = (MODE == 1) ? ((n % Dm1) >= k) : ((n % D) > (k % Dm1));
        Wt[(size_t)n * K + k] = __float2half(keep ? v : 0.f);
    }
}

__global__ void zp_h_kernel(const float* __restrict__ z,
                            const int* __restrict__ perm,
                            int Brows, int D) {
    int idx = blockIdx.x * blockDim.x + threadIdx.x;
    if (idx < Brows * D) {
        int b = idx / D;
        int d = idx - b * D;
        g_zph[idx] = __float2half(z[(size_t)b * D + perm[d]]);
    }
}

// MODE 1: A=g_zph, B=g_w1t, bias+relu -> g_ht (fp16)
// MODE 2: A=g_ht,  B=g_w2t, bias      -> g_res (f32)
template <int MODE>
__global__ void __launch_bounds__(NTH)
gemm_cp(const float* __restrict__ bias, int N, int K, int D)
{
    const __half* __restrict__ A  = (MODE == 1) ? g_zph : g_ht;
    const __half* __restrict__ Bt = (MODE == 1) ? g_w1t : g_w2t;

    extern __shared__ char sm[];
    const uint32_t smu = smem_u32(sm);

    const int tid  = threadIdx.x;
    const int wid  = tid >> 5;
    const int lane = tid & 31;
    const int gq   = lane >> 2;
    const int tq   = lane & 3;
    const int row0 = blockIdx.x * BM;   // M fast
    const int col0 = blockIdx.y * BN;
    const int Dm1  = D - 1;

    const int mwarp = (wid & 1) * 64;
    const int nwarp = (wid >> 1) * 32;

    // ---- tile-skip bounds ----
    int maxkey;
    if (MODE == 1) {
        int m0 = col0 % Dm1;
        maxkey = (m0 + BN - 1 >= Dm1) ? (Dm1 - 1) : (m0 + BN - 1);
    } else {
        maxkey = (col0 % D) + BN - 1;
    }
    const int nT = K / BK;
    const int nT1 = (MODE == 1) ? min(nT, maxkey / BK + 1) : nT;

    // ---- cp.async maps: 2 A-chunks + 2 B-chunks (16B) per thread per stage ----
    uint32_t adst[2], bdst[2];
    const __half* asrc[2];
    const __half* bsrc[2];
#pragma unroll
    for (int i = 0; i < 2; i++) {
        int slot = tid + i * NTH;        // 0..511
        int r  = slot >> 2;              // row 0..127
        int cc = slot & 3;               // 16B chunk (4 words)
        uint32_t off = (uint32_t)((r << 6) + (((cc << 2) ^ (((r >> 1) & 3) << 2)) << 2));
        adst[i] = smu + off;
        bdst[i] = smu + 8192 + off;
        asrc[i] = A  + (size_t)(row0 + r) * K + cc * 8;
        bsrc[i] = Bt + (size_t)(col0 + r) * K + cc * 8;
    }

    float acc[4][4][4];
#pragma unroll
    for (int mt = 0; mt < 4; mt++)
#pragma unroll
        for (int nt = 0; nt < 4; nt++)
#pragma unroll
            for (int e = 0; e < 4; e++) acc[mt][nt][e] = 0.f;

    // next active tile after t
    auto nxt = [&](int t) -> int {
        int tn = t + 1;
        if (MODE == 1) return (tn >= nT1) ? nT : tn;
        while (tn < nT) {
            int r = (tn * BK) % Dm1;
            int minh = (r + BK - 1 > Dm1 - 1) ? 0 : r;   // wrap hits 0
            if (minh < maxkey) break;
            tn++;
        }
        return tn;
    };

#define ISSUE(T, S)                                                   \
    {                                                                  \
        if ((T) < nT) {                                                \
            uint32_t base_ = (uint32_t)((S) * STG_BYTES);              \
            const int ko_ = (T) * BK;                                  \
            CPA16(adst[0] + base_, asrc[0] + ko_);                     \
            CPA16(adst[1] + base_, asrc[1] + ko_);                     \
            CPA16(bdst[0] + base_, bsrc[0] + ko_);                     \
            CPA16(bdst[1] + base_, bsrc[1] + ko_);                     \
        }                                                              \
        CPA_COMMIT();                                                  \
    }

    // ---- prologue: stage first 3 active tiles ----
    int t0 = 0;
    int t1 = nxt(t0);
    int t2 = (t1 < nT) ? nxt(t1) : nT;
    ISSUE(t0, 0);
    ISSUE(t1, 1);
    ISSUE(t2, 2);
    int tIss = t2;

    int tc = 0, p = 0;
    while (tc < nT) {
        __syncthreads();                       // buffer (p+3)%4 free of readers
        tIss = (tIss < nT) ? nxt(tIss) : nT;
        ISSUE(tIss, (p + 3) & 3);
        CPA_WAIT2();
        __syncthreads();

        const uint32_t ab = smu + (uint32_t)((p & 3) * STG_BYTES);
        const uint32_t bb = ab + 8192;
        uint32_t af[2][4][4], bf[2][4][2];
#pragma unroll
        for (int ks = 0; ks < 2; ks++) {
            const int kpl = ks * 8 + tq;
            const int kph = kpl + 4;
#pragma unroll
            for (int mt = 0; mt < 4; mt++) {
                int m_ = mwarp + mt * 16 + gq;
                af[ks][mt][0] = ldsw(ab + woff(m_,     kpl));
                af[ks][mt][1] = ldsw(ab + woff(m_ + 8, kpl));
                af[ks][mt][2] = ldsw(ab + woff(m_,     kph));
                af[ks][mt][3] = ldsw(ab + woff(m_ + 8, kph));
            }
#pragma unroll
            for (int nt = 0; nt < 4; nt++) {
                int n_ = nwarp + nt * 8 + gq;
                bf[ks][nt][0] = ldsw(bb + woff(n_, kpl));
                bf[ks][nt][1] = ldsw(bb + woff(n_, kph));
            }
        }
#pragma unroll
        for (int ks = 0; ks < 2; ks++)
#pragma unroll
            for (int mt = 0; mt < 4; mt++)
#pragma unroll
                for (int nt = 0; nt < 4; nt++)
                    mma16(acc[mt][nt],
                          af[ks][mt][0], af[ks][mt][1], af[ks][mt][2], af[ks][mt][3],
                          bf[ks][nt][0], bf[ks][nt][1]);

        tc = nxt(tc);
        p++;
    }
#undef ISSUE

    // ---- epilogue ----
#pragma unroll
    for (int mt = 0; mt < 4; mt++) {
        int r0 = row0 + mwarp + mt * 16 + gq;
#pragma unroll
        for (int nt = 0; nt < 4; nt++) {
            int c = col0 + nwarp + nt * 8 + 2 * tq;
            float bx = bias[c], by = bias[c + 1];
            float v00 = acc[mt][nt][0] + bx, v01 = acc[mt][nt][1] + by;
            float v10 = acc[mt][nt][2] + bx, v11 = acc[mt][nt][3] + by;
            if (MODE == 1) {
                v00 = fmaxf(v00, 0.f); v01 = fmaxf(v01, 0.f);
                v10 = fmaxf(v10, 0.f); v11 = fmaxf(v11, 0.f);
                *(uint32_t*)(&g_ht[(size_t)r0 * N + c])       = h2pack(v00, v01);
                *(uint32_t*)(&g_ht[(size_t)(r0 + 8) * N + c]) = h2pack(v10, v11);
            } else {
                float2 a0; a0.x = v00; a0.y = v01;
                float2 a1; a1.x = v10; a1.y = v11;
                *(float2*)(&g_res[(size_t)r0 * N + c])       = a0;
                *(float2*)(&g_res[(size_t)(r0 + 8) * N + c]) = a1;
            }
        }
    }
}

__global__ void finish_kernel(const float* __restrict__ z,
                              const int* __restrict__ perm,
                              float* __restrict__ out,
                              int Brows, int D, int out_size)
{
    int b = blockIdx.x;
    int tid = threadIdx.x;
    const float* mu = g_res + (size_t)b * 2 * D;
    const float* ls = mu + D;
    const float* zrow = z + (size_t)b * D;

    float partial = 0.f;
    for (int d = tid; d < D; d += blockDim.x) {
        float l = ls[d];
        float x = zrow[perm[d]] * expf(l) + mu[d];   // zp[b][d] = z[b][perm[d]]
        out[(size_t)b * D + perm[d]] = x;
        partial += l;
    }

    __shared__ float red[256];
    red[tid] = partial;
    __syncthreads();
    for (int s = 128; s > 0; s >>= 1) {
        if (tid < s) red[tid] += red[tid + s];
        __syncthreads();
    }
    if (tid == 0 && out_size >= Brows * D + Brows)
        out[(size_t)Brows * D + b] = red[0];
}

extern "C" void kernel_launch(void* const* d_in, const int* in_sizes, int n_in,
                              void* d_out, int out_size)
{
    const float* z   = (const float*)d_in[0];
    const float* W1  = (const float*)d_in[1];
    const float* b1  = (const float*)d_in[2];
    const float* W2  = (const float*)d_in[3];
    const float* b2  = (const float*)d_in[4];
    const int*  perm = (const int*)d_in[5];

    const int D     = in_sizes[5];          // 1024
    const int H     = in_sizes[2];          // 4096
    const int Brows = in_sizes[0] / D;      // 4096
    const int N2    = in_sizes[4];          // 2048

    float* out = (float*)d_out;

    static bool attr_set = false;
    if (!attr_set) {
        cudaFuncSetAttribute(gemm_cp<1>, cudaFuncAttributeMaxDynamicSharedMemorySize, SMEM_TOTAL);
        cudaFuncSetAttribute(gemm_cp<2>, cudaFuncAttributeMaxDynamicSharedMemorySize, SMEM_TOTAL);
        attr_set = true;
    }

    // prep: masked fp16 transposed weights + fp16 zp
    {
        __half* w1t; cudaGetSymbolAddress((void**)&w1t, g_w1t);
        __half* w2t; cudaGetSymbolAddress((void**)&w2t, g_w2t);
        dim3 blk(32, 8);
        dim3 gw1(D / 32, H / 32);
        wt_kernel<1><<<gw1, blk>>>(W1, w1t, D, H, D);
        dim3 gw2(H / 32, N2 / 32);
        wt_kernel<2><<<gw2, blk>>>(W2, w2t, H, N2, D);
    }
    zp_h_kernel<<<(Brows * D + 255) / 256, 256>>>(z, perm, Brows, D);

    dim3 g1(Brows / BM, H / BN);
    gemm_cp<1><<<g1, NTH, SMEM_TOTAL>>>(b1, H, D, D);

    dim3 g2(Brows / BM, N2 / BN);
    gemm_cp<2><<<g2, NTH, SMEM_TOTAL>>>(b2, N2, H, D);

    finish_kernel<<<Brows, 256>>>(z, perm, out, Brows, D, out_size);
}

// round 13
// speedup vs baseline: 2.0345x; 1.0188x over previous
#include <cuda_runtime.h>
#include <cuda_fp16.h>
#include <math.h>
#include <stdint.h>

// MADE/IAF layer, fp16 mma.sync m16n8k16 + cp.async pipeline + ldmatrix.
//   zp = z[:, perm]
//   h  = relu(zp @ (W1*M1) + b1)          M=4096 K=1024 N=4096
//   r  = h @ (W2*M2) + b2                 M=4096 K=4096 N=2048
//   x  = zp*exp(log_s)+mu ; scatter by perm ; log_det = sum(log_s)
// Masks baked into transposed fp16 weights at prep time.
// All-zero masked B k-tiles skipped (exact-zero contributions).

#define BM 128
#define BN 128
#define BK 32
#define NTH 256
#define NSTG 4
#define STG_BYTES 16384           // A 8KB + B 8KB per stage
#define SMEM_TOTAL (NSTG * STG_BYTES)

__device__ __half g_zph[4096L * 1024];   //  8.4 MB  zp fp16 [m][D]
__device__ __half g_ht [4096L * 4096];   // 33.6 MB  h  fp16 [m][H]
__device__ __half g_w1t[4096L * 1024];   //  8.4 MB  (W1*M1)^T fp16 [H][D]
__device__ __half g_w2t[2048L * 4096];   // 16.8 MB  (W2*M2)^T fp16 [2D][H]
__device__ float  g_res[4096L * 2048];   // 33.6 MB

__device__ __forceinline__ uint32_t smem_u32(const void* p) {
    uint32_t a;
    asm("{ .reg .u64 t; cvta.to.shared.u64 t, %1; cvt.u32.u64 %0, t; }" : "=r"(a) : "l"(p));
    return a;
}
__device__ __forceinline__ uint32_t h2pack(float lo, float hi) {
    uint32_t w;
    asm("cvt.rn.f16x2.f32 %0, %1, %2;" : "=r"(w) : "f"(hi), "f"(lo));
    return w;
}
__device__ __forceinline__ void mma16(float* d,
                                      uint32_t a0, uint32_t a1, uint32_t a2, uint32_t a3,
                                      uint32_t b0, uint32_t b1) {
    asm volatile(
        "mma.sync.aligned.m16n8k16.row.col.f32.f16.f16.f32 "
        "{%0,%1,%2,%3}, {%4,%5,%6,%7}, {%8,%9}, {%0,%1,%2,%3};"
        : "+f"(d[0]), "+f"(d[1]), "+f"(d[2]), "+f"(d[3])
        : "r"(a0), "r"(a1), "r"(a2), "r"(a3), "r"(b0), "r"(b1));
}
__device__ __forceinline__ void ldm4(uint32_t& r0, uint32_t& r1,
                                     uint32_t& r2, uint32_t& r3, uint32_t addr) {
    asm volatile("ldmatrix.sync.aligned.m8n8.x4.shared.b16 {%0,%1,%2,%3}, [%4];"
                 : "=r"(r0), "=r"(r1), "=r"(r2), "=r"(r3) : "r"(addr));
}
#define CPA16(dst, src) \
    asm volatile("cp.async.cg.shared.global [%0], [%1], 16;" :: "r"(dst), "l"(src))
#define CPA_COMMIT() asm volatile("cp.async.commit_group;" ::: "memory")
#define CPA_WAIT2()  asm volatile("cp.async.wait_group 2;" ::: "memory")

// ---- prep: masked transpose W[K][N] -> Wt[N][K] fp16 ----
template <int MODE>
__global__ void wt_kernel(const float* __restrict__ W, __half* __restrict__ Wt,
                          int K, int N, int D)
{
    __shared__ float tile[32][33];
    int k0 = blockIdx.x * 32, n0 = blockIdx.y * 32;
    int x = threadIdx.x, y = threadIdx.y;    // 32 x 8
#pragma unroll
    for (int r = 0; r < 32; r += 8)
        tile[y + r][x] = W[(size_t)(k0 + y + r) * N + n0 + x];
    __syncthreads();
    int Dm1 = D - 1;
#pragma unroll
    for (int r = 0; r < 32; r += 8) {
        int n = n0 + y + r, k = k0 + x;
        float v = tile[x][y + r];
        bool keep = (MODE == 1) ? ((n % Dm1) >= k) : ((n % D) > (k % Dm1));
        Wt[(size_t)n * K + k] = __float2half(keep ? v : 0.f);
    }
}

__global__ void zp_h_kernel(const float* __restrict__ z,
                            const int* __restrict__ perm,
                            int Brows, int D) {
    int idx = blockIdx.x * blockDim.x + threadIdx.x;
    if (idx < Brows * D) {
        int b = idx / D;
        int d = idx - b * D;
        g_zph[idx] = __float2half(z[(size_t)b * D + perm[d]]);
    }
}

// MODE 1: A=g_zph, B=g_w1t, bias+relu -> g_ht (fp16)
// MODE 2: A=g_ht,  B=g_w2t, bias      -> g_res (f32)
template <int MODE>
__global__ void __launch_bounds__(NTH)
gemm_cp(const float* __restrict__ bias, int N, int K, int D)
{
    const __half* __restrict__ A  = (MODE == 1) ? g_zph : g_ht;
    const __half* __restrict__ Bt = (MODE == 1) ? g_w1t : g_w2t;

    extern __shared__ char sm[];
    const uint32_t smu = smem_u32(sm);

    const int tid  = threadIdx.x;
    const int wid  = tid >> 5;
    const int lane = tid & 31;
    const int gq   = lane >> 2;
    const int tq   = lane & 3;
    const int row0 = blockIdx.x * BM;   // M fast
    const int col0 = blockIdx.y * BN;
    const int Dm1  = D - 1;

    const int mwarp = (wid & 1) * 64;
    const int nwarp = (wid >> 1) * 32;

    // ---- tile-skip bounds ----
    int maxkey;
    if (MODE == 1) {
        int m0 = col0 % Dm1;
        maxkey = (m0 + BN - 1 >= Dm1) ? (Dm1 - 1) : (m0 + BN - 1);
    } else {
        maxkey = (col0 % D) + BN - 1;
    }
    const int nT = K / BK;
    const int nT1 = (MODE == 1) ? min(nT, maxkey / BK + 1) : nT;

    // ---- cp.async maps: 2 A-chunks + 2 B-chunks (16B) per thread per stage ----
    uint32_t adst[2], bdst[2];
    const __half* asrc[2];
    const __half* bsrc[2];
#pragma unroll
    for (int i = 0; i < 2; i++) {
        int slot = tid + i * NTH;        // 0..511
        int r  = slot >> 2;              // row 0..127
        int cc = slot & 3;               // 16B chunk
        uint32_t off = (uint32_t)((r << 6) + ((cc ^ ((r >> 1) & 3)) << 4));
        adst[i] = smu + off;
        bdst[i] = smu + 8192 + off;
        asrc[i] = A  + (size_t)(row0 + r) * K + cc * 8;
        bsrc[i] = Bt + (size_t)(col0 + r) * K + cc * 8;
    }

    // ---- ldmatrix lane address components ----
    // A frag (mt, ks): mats [m0-7|ck0, m8-15|ck0, m0-7|ck1, m8-15|ck1]
    const int mat = lane >> 3;
    const int arow_off = ((mat & 1) << 3) + (lane & 7);
    const int ackbit   = mat >> 1;
    // B frag (ntpair, ks): mats [n0-7|ck0, n0-7|ck1, n8-15|ck0, n8-15|ck1]
    const int brow_off = ((mat >> 1) << 3) + (lane & 7);
    const int bckbit   = mat & 1;

    uint32_t abase[4]; int aswz[4];
#pragma unroll
    for (int mt = 0; mt < 4; mt++) {
        int r = mwarp + mt * 16 + arow_off;
        abase[mt] = (uint32_t)(r << 6);
        aswz[mt]  = (r >> 1) & 3;
    }
    uint32_t bbase[2]; int bswz[2];
#pragma unroll
    for (int np = 0; np < 2; np++) {
        int r = nwarp + np * 16 + brow_off;
        bbase[np] = (uint32_t)(r << 6);
        bswz[np]  = (r >> 1) & 3;
    }

    float acc[4][4][4];
#pragma unroll
    for (int mt = 0; mt < 4; mt++)
#pragma unroll
        for (int nt = 0; nt < 4; nt++)
#pragma unroll
            for (int e = 0; e < 4; e++) acc[mt][nt][e] = 0.f;

    auto nxt = [&](int t) -> int {
        int tn = t + 1;
        if (MODE == 1) return (tn >= nT1) ? nT : tn;
        while (tn < nT) {
            int r = (tn * BK) % Dm1;
            int minh = (r + BK - 1 > Dm1 - 1) ? 0 : r;   // wrap hits 0
            if (minh < maxkey) break;
            tn++;
        }
        return tn;
    };

#define ISSUE(T, S)                                                   \
    {                                                                  \
        if ((T) < nT) {                                                \
            uint32_t base_ = (uint32_t)((S) * STG_BYTES);              \
            const int ko_ = (T) * BK;                                  \
            CPA16(adst[0] + base_, asrc[0] + ko_);                     \
            CPA16(adst[1] + base_, asrc[1] + ko_);                     \
            CPA16(bdst[0] + base_, bsrc[0] + ko_);                     \
            CPA16(bdst[1] + base_, bsrc[1] + ko_);                     \
        }                                                              \
        CPA_COMMIT();                                                  \
    }

    // ---- prologue: stage first 3 active tiles (groups 0..2 = stages 0..2) ----
    int t0 = 0;
    int t1 = nxt(t0);
    int t2 = (t1 < nT) ? nxt(t1) : nT;
    ISSUE(t0, 0);
    ISSUE(t1, 1);
    ISSUE(t2, 2);
    int tIss = t2;

    int tc = 0, p = 0;
    while (tc < nT) {
        CPA_WAIT2();                 // stage p landed
        __syncthreads();             // readers of slot (p-1)&3 (iter p-1) retired
        tIss = (tIss < nT) ? nxt(tIss) : nT;
        ISSUE(tIss, (p + 3) & 3);    // (p+3)&3 == (p-1)&3

        const uint32_t ab = smu + (uint32_t)((p & 3) * STG_BYTES);
        const uint32_t bb = ab + 8192;

        uint32_t af[2][4][4], bf[2][4][2];
#pragma unroll
        for (int ks = 0; ks < 2; ks++) {
            const int ack = (ks * 2 + ackbit);
            const int bck = (ks * 2 + bckbit);
#pragma unroll
            for (int mt = 0; mt < 4; mt++)
                ldm4(af[ks][mt][0], af[ks][mt][1], af[ks][mt][2], af[ks][mt][3],
                     ab + abase[mt] + (uint32_t)(((ack ^ aswz[mt]) & 3) << 4));
#pragma unroll
            for (int np = 0; np < 2; np++)
                ldm4(bf[ks][2 * np][0], bf[ks][2 * np][1],
                     bf[ks][2 * np + 1][0], bf[ks][2 * np + 1][1],
                     bb + bbase[np] + (uint32_t)(((bck ^ bswz[np]) & 3) << 4));
        }
#pragma unroll
        for (int ks = 0; ks < 2; ks++)
#pragma unroll
            for (int mt = 0; mt < 4; mt++)
#pragma unroll
                for (int nt = 0; nt < 4; nt++)
                    mma16(acc[mt][nt],
                          af[ks][mt][0], af[ks][mt][1], af[ks][mt][2], af[ks][mt][3],
                          bf[ks][nt][0], bf[ks][nt][1]);

        tc = nxt(tc);
        p++;
    }
#undef ISSUE

    // ---- epilogue ----
#pragma unroll
    for (int mt = 0; mt < 4; mt++) {
        int r0 = row0 + mwarp + mt * 16 + gq;
#pragma unroll
        for (int nt = 0; nt < 4; nt++) {
            int c = col0 + nwarp + nt * 8 + 2 * tq;
            float bx = bias[c], by = bias[c + 1];
            float v00 = acc[mt][nt][0] + bx, v01 = acc[mt][nt][1] + by;
            float v10 = acc[mt][nt][2] + bx, v11 = acc[mt][nt][3] + by;
            if (MODE == 1) {
                v00 = fmaxf(v00, 0.f); v01 = fmaxf(v01, 0.f);
                v10 = fmaxf(v10, 0.f); v11 = fmaxf(v11, 0.f);
                *(uint32_t*)(&g_ht[(size_t)r0 * N + c])       = h2pack(v00, v01);
                *(uint32_t*)(&g_ht[(size_t)(r0 + 8) * N + c]) = h2pack(v10, v11);
            } else {
                float2 a0; a0.x = v00; a0.y = v01;
                float2 a1; a1.x = v10; a1.y = v11;
                *(float2*)(&g_res[(size_t)r0 * N + c])       = a0;
                *(float2*)(&g_res[(size_t)(r0 + 8) * N + c]) = a1;
            }
        }
    }
}

__global__ void finish_kernel(const float* __restrict__ z,
                              const int* __restrict__ perm,
                              float* __restrict__ out,
                              int Brows, int D, int out_size)
{
    int b = blockIdx.x;
    int tid = threadIdx.x;
    const float* mu = g_res + (size_t)b * 2 * D;
    const float* ls = mu + D;
    const float* zrow = z + (size_t)b * D;

    float partial = 0.f;
    for (int d = tid; d < D; d += blockDim.x) {
        float l = ls[d];
        float x = zrow[perm[d]] * expf(l) + mu[d];
        out[(size_t)b * D + perm[d]] = x;
        partial += l;
    }

    __shared__ float red[256];
    red[tid] = partial;
    __syncthreads();
    for (int s = 128; s > 0; s >>= 1) {
        if (tid < s) red[tid] += red[tid + s];
        __syncthreads();
    }
    if (tid == 0 && out_size >= Brows * D + Brows)
        out[(size_t)Brows * D + b] = red[0];
}

extern "C" void kernel_launch(void* const* d_in, const int* in_sizes, int n_in,
                              void* d_out, int out_size)
{
    const float* z   = (const float*)d_in[0];
    const float* W1  = (const float*)d_in[1];
    const float* b1  = (const float*)d_in[2];
    const float* W2  = (const float*)d_in[3];
    const float* b2  = (const float*)d_in[4];
    const int*  perm = (const int*)d_in[5];

    const int D     = in_sizes[5];          // 1024
    const int H     = in_sizes[2];          // 4096
    const int Brows = in_sizes[0] / D;      // 4096
    const int N2    = in_sizes[4];          // 2048

    float* out = (float*)d_out;

    static bool attr_set = false;
    if (!attr_set) {
        cudaFuncSetAttribute(gemm_cp<1>, cudaFuncAttributeMaxDynamicSharedMemorySize, SMEM_TOTAL);
        cudaFuncSetAttribute(gemm_cp<2>, cudaFuncAttributeMaxDynamicSharedMemorySize, SMEM_TOTAL);
        attr_set = true;
    }

    {
        __half* w1t; cudaGetSymbolAddress((void**)&w1t, g_w1t);
        __half* w2t; cudaGetSymbolAddress((void**)&w2t, g_w2t);
        dim3 blk(32, 8);
        dim3 gw1(D / 32, H / 32);
        wt_kernel<1><<<gw1, blk>>>(W1, w1t, D, H, D);
        dim3 gw2(H / 32, N2 / 32);
        wt_kernel<2><<<gw2, blk>>>(W2, w2t, H, N2, D);
    }
    zp_h_kernel<<<(Brows * D + 255) / 256, 256>>>(z, perm, Brows, D);

    dim3 g1(Brows / BM, H / BN);
    gemm_cp<1><<<g1, NTH, SMEM_TOTAL>>>(b1, H, D, D);

    dim3 g2(Brows / BM, N2 / BN);
    gemm_cp<2><<<g2, NTH, SMEM_TOTAL>>>(b2, N2, H, D);

    finish_kernel<<<Brows, 256>>>(z, perm, out, Brows, D, out_size);
}